// round 15
// baseline (speedup 1.0000x reference)
#include <cuda_runtime.h>
#include <cuda_fp16.h>
#include <cstdint>

// ---------------- problem constants ----------------
#define CIN     2112
#define COUT    192
#define HW      49
#define M_TOTAL 12544          // 256*49
#define BM      64
#define BN      64
#define BK      64
#define CHUNKS  33             // 2112/64
#define NTH     128            // 4 warps, warp tile 32x32
#define EPS_BN  1e-5f

// smem: row stride 144B (64 halfs + 16B pad; 16B-aligned, conflict-free)
#define RSTB    144
#define A_STAGE (BM * RSTB)            // 9216 B
#define B_STAGE (BN * RSTB)            // 9216 B
#define SM_A    0                      // 2 stages
#define SM_B    (2 * A_STAGE)
#define SMEM_TOTAL (SM_B + 2 * B_STAGE)  // 36864 B -> 4+ CTAs/SM
#define CST     66                     // epilogue Cs row stride (floats)

// ---------------- persistent scratch ----------------
__device__ __half g_wh[COUT * CIN];    // W fp16, k-major
__device__ float2 g_bn[CIN];           // {scale, shift} fp32

__global__ void prep_k(const float* __restrict__ W,
                       const float* __restrict__ gamma, const float* __restrict__ beta,
                       const float* __restrict__ mean,  const float* __restrict__ var) {
    int i = blockIdx.x * blockDim.x + threadIdx.x;
    if (i < COUT * CIN) g_wh[i] = __float2half_rn(W[i]);
    if (i < CIN) {
        float inv = rsqrtf(var[i] + EPS_BN);
        float s = gamma[i] * inv;
        g_bn[i] = make_float2(s, fmaf(-mean[i], s, beta[i]));
    }
}

// ---------------- helpers ----------------
__device__ __forceinline__ uint32_t smem_u32(const void* p) {
    uint32_t a;
    asm("{ .reg .u64 t; cvta.to.shared.u64 t, %1; cvt.u32.u64 %0, t; }" : "=r"(a) : "l"(p));
    return a;
}
__device__ __forceinline__ void cp16(uint32_t dst, const void* src) {
    asm volatile("cp.async.cg.shared.global [%0], [%1], 16;" :: "r"(dst), "l"(src));
}
__device__ __forceinline__ void ldm_x4(uint32_t* r, uint32_t addr) {
    asm volatile("ldmatrix.sync.aligned.m8n8.x4.shared.b16 {%0,%1,%2,%3}, [%4];"
                 : "=r"(r[0]), "=r"(r[1]), "=r"(r[2]), "=r"(r[3]) : "r"(addr));
}

// ---------------- fused BN+ReLU + fp16 GEMM ----------------
// C[M=12544, N=192] = relu(x*s+t)[M, K] * W[N, K]^T
// grid 588 = 196 m-tiles x 3 n-tiles (n-triples of one m-tile adjacent -> share x via L2)
__global__ __launch_bounds__(NTH, 4)
void gemm_k(const float* __restrict__ x, float* __restrict__ out) {
    extern __shared__ char smem[];
    const uint32_t sA = smem_u32(smem) + SM_A;
    const uint32_t sB = smem_u32(smem) + SM_B;

    const int tid  = threadIdx.x;
    const int lane = tid & 31, warp = tid >> 5;     // 4 warps
    const int wm = warp & 1, wn = warp >> 1;        // 2 x 2 warp grid, tile 32x32
    const int g  = lane >> 2, tq = lane & 3;

    const int mt = blockIdx.x / 3, nt = blockIdx.x - mt * 3;
    const int m0 = mt * BM;
    const int n0 = nt * BN;

    // A loader: thread -> (m = tid&63, 32 k at kh*32), staged in two 16-k halves
    const int am = tid & 63, kh = tid >> 6;
    const int mg = m0 + am;
    const float* xp = x + (size_t)(mg / HW) * ((size_t)CIN * HW) + (mg % HW)
                        + (size_t)(kh * 32) * HW;

    const __half* bsrc = g_wh + (size_t)n0 * CIN;

    // ldmatrix per-thread offsets within a stage
    const uint32_t offA = (uint32_t)(wm * 32 + (lane & 15)) * RSTB + (uint32_t)(lane >> 4) * 16u;
    uint32_t offB[2];
    #pragma unroll
    for (int j = 0; j < 2; j++)
        offB[j] = (uint32_t)(wn * 32 + j * 16 + ((lane >> 4) << 3) + (lane & 7)) * RSTB
                + (uint32_t)((lane >> 3) & 1) * 16u;

    float acc[2][4][4] = {};
    float ar[16];
    uint32_t af[2][2][4], bf[2][2][4];     // double-buffered fragments

    // B cp.async for one chunk: 64 rows x 8 packets = 512 = 4 x 128
    auto issueB = [&](int c, uint32_t bb) {
        const __half* bw = bsrc + (size_t)c * BK;
        #pragma unroll
        for (int i = 0; i < 4; i++) {
            const int q = tid + i * NTH, r = q >> 3, p = q & 7;
            cp16(bb + r * RSTB + p * 16, bw + (size_t)r * CIN + p * 8);
        }
    };
    auto ldgA = [&](int c, int hf) {
        const float* xp2 = xp + (size_t)(c * BK + hf * 16) * HW;
        #pragma unroll
        for (int j = 0; j < 16; j++) ar[j] = __ldg(xp2 + (size_t)j * HW);
    };
    auto stsA = [&](int c, int hf) {
        const int k0 = c * BK + kh * 32 + hf * 16;
        __half h[16];
        #pragma unroll
        for (int j = 0; j < 16; j++) {
            const float2 s = __ldg(&g_bn[k0 + j]);
            h[j] = __float2half_rn(fmaxf(fmaf(ar[j], s.x, s.y), 0.f));
        }
        char* ab = smem + SM_A + (c & 1) * A_STAGE + am * RSTB + kh * 64 + hf * 32;
        *(uint4*)(ab)      = *(uint4*)&h[0];
        *(uint4*)(ab + 16) = *(uint4*)&h[8];
    };

    // load step-s fragments into buffer buf
    auto loadfrag = [&](uint32_t aBase, uint32_t bBase, int s, int buf) {
        ldm_x4(af[buf][0], aBase + offA + s * 32);
        ldm_x4(af[buf][1], aBase + offA + 16 * RSTB + s * 32);
        #pragma unroll
        for (int j = 0; j < 2; j++) ldm_x4(bf[buf][j], bBase + offB[j] + s * 32);
    };
    // issue the 8 MMAs for buffer buf
    auto mmastep = [&](int buf) {
        #pragma unroll
        for (int mi = 0; mi < 2; mi++)
            #pragma unroll
            for (int ni = 0; ni < 4; ni++) {
                const uint32_t* bp = &bf[buf][ni >> 1][(ni & 1) * 2];
                asm volatile(
                    "mma.sync.aligned.m16n8k16.row.col.f32.f16.f16.f32 "
                    "{%0,%1,%2,%3},{%4,%5,%6,%7},{%8,%9},{%0,%1,%2,%3};"
                    : "+f"(acc[mi][ni][0]), "+f"(acc[mi][ni][1]),
                      "+f"(acc[mi][ni][2]), "+f"(acc[mi][ni][3])
                    : "r"(af[buf][mi][0]), "r"(af[buf][mi][1]),
                      "r"(af[buf][mi][2]), "r"(af[buf][mi][3]),
                      "r"(bp[0]), "r"(bp[1]));
            }
    };

    // ---- prologue: stage chunk 0 ----
    issueB(0, sB);
    asm volatile("cp.async.commit_group;");
    ldgA(0, 0); stsA(0, 0);
    ldgA(0, 1); stsA(0, 1);
    asm volatile("cp.async.wait_group 0;");
    __syncthreads();

    // ---- main loop (fragment double-buffered) ----
    #pragma unroll 1
    for (int t = 0; t < CHUNKS; t++) {
        const int cur = t & 1, nxt = cur ^ 1;
        const bool more = (t + 1 < CHUNKS);
        const uint32_t aBase = sA + cur * A_STAGE;
        const uint32_t bBase = sB + cur * B_STAGE;

        loadfrag(aBase, bBase, 0, 0);

        if (more) {
            ldgA(t + 1, 0);
            issueB(t + 1, sB + nxt * B_STAGE);
        }
        asm volatile("cp.async.commit_group;");

        loadfrag(aBase, bBase, 1, 1);
        mmastep(0);
        if (more) { stsA(t + 1, 0); ldgA(t + 1, 1); }
        loadfrag(aBase, bBase, 2, 0);
        mmastep(1);
        loadfrag(aBase, bBase, 3, 1);
        mmastep(0);
        if (more) stsA(t + 1, 1);
        mmastep(1);

        asm volatile("cp.async.wait_group 0;");
        __syncthreads();
    }

    // ---- epilogue: acc -> Cs[n][m] in smem -> coalesced STG ----
    float* Cs = (float*)smem;                    // 64 x 66 floats (reuses smem)
    #pragma unroll
    for (int mi = 0; mi < 2; mi++)
        #pragma unroll
        for (int hh = 0; hh < 2; hh++) {
            const int mloc = wm * 32 + mi * 16 + g + hh * 8;
            #pragma unroll
            for (int ni = 0; ni < 4; ni++) {
                const int nloc = wn * 32 + ni * 8 + tq * 2;
                Cs[nloc * CST + mloc]       = acc[mi][ni][hh * 2 + 0];
                Cs[(nloc + 1) * CST + mloc] = acc[mi][ni][hh * 2 + 1];
            }
        }
    __syncthreads();

    // each warp writes 16 n-rows; lane covers m = 2*lane, 2*lane+1 (hw-contiguous)
    {
        const int mg0 = m0 + lane * 2;
        const int b0_ = mg0 / HW,        hw0 = mg0 - b0_ * HW;
        const int b1_ = (mg0 + 1) / HW,  hw1 = (mg0 + 1) - b1_ * HW;
        #pragma unroll
        for (int r = 0; r < 16; r++) {
            const int nn = n0 + warp * 16 + r;
            const float2 v = *(const float2*)&Cs[(warp * 16 + r) * CST + lane * 2];
            out[((size_t)b0_ * COUT + nn) * HW + hw0] = v.x;
            out[((size_t)b1_ * COUT + nn) * HW + hw1] = v.y;
        }
    }
}

extern "C" void kernel_launch(void* const* d_in, const int* in_sizes, int n_in,
                              void* d_out, int out_size) {
    const float* x     = (const float*)d_in[0];
    const float* gamma = (const float*)d_in[1];
    const float* beta  = (const float*)d_in[2];
    const float* mean  = (const float*)d_in[3];
    const float* var   = (const float*)d_in[4];
    const float* W     = (const float*)d_in[5];
    float* out = (float*)d_out;

    prep_k<<<(COUT * CIN + 255) / 256, 256>>>(W, gamma, beta, mean, var);
    cudaFuncSetAttribute(gemm_k, cudaFuncAttributeMaxDynamicSharedMemorySize, SMEM_TOTAL);
    gemm_k<<<(M_TOTAL / BM) * 3, NTH, SMEM_TOTAL>>>(x, out);
}

// round 16
// speedup vs baseline: 1.0402x; 1.0402x over previous
#include <cuda_runtime.h>
#include <cuda_fp16.h>
#include <cstdint>

// ---------------- problem constants ----------------
#define CIN     2112
#define COUT    192
#define HW      49
#define M_TOTAL 12544          // 256*49
#define BM      64
#define BN      96
#define BK      64
#define CHUNKS  33             // 2112/64
#define NTH     128            // 4 warps, warp tile 32x48
#define EPS_BN  1e-5f

// smem: row stride 144B (64 halfs + 16B pad; 16B-aligned, conflict-free)
#define RSTB    144
#define A_STAGE (BM * RSTB)            // 9216 B
#define B_STAGE (BN * RSTB)            // 13824 B
#define SM_BNS  0                      // float2[2112] = 16896 B
#define SM_A    16896                  // 2 stages
#define SM_B    (SM_A + 2 * A_STAGE)
#define SMEM_TOTAL (SM_B + 2 * B_STAGE)  // 62976 B -> 3 CTAs/SM
#define CST     66                     // epilogue Cs row stride (floats)

// ---------------- persistent scratch ----------------
__device__ __half g_wh[COUT * CIN];    // W fp16, k-major

__global__ void prep_w_k(const float* __restrict__ W) {
    int i = blockIdx.x * blockDim.x + threadIdx.x;
    if (i < COUT * CIN) g_wh[i] = __float2half_rn(W[i]);
}

// ---------------- helpers ----------------
__device__ __forceinline__ uint32_t smem_u32(const void* p) {
    uint32_t a;
    asm("{ .reg .u64 t; cvta.to.shared.u64 t, %1; cvt.u32.u64 %0, t; }" : "=r"(a) : "l"(p));
    return a;
}
__device__ __forceinline__ void cp16(uint32_t dst, const void* src) {
    asm volatile("cp.async.cg.shared.global [%0], [%1], 16;" :: "r"(dst), "l"(src));
}
__device__ __forceinline__ void ldm_x4(uint32_t* r, uint32_t addr) {
    asm volatile("ldmatrix.sync.aligned.m8n8.x4.shared.b16 {%0,%1,%2,%3}, [%4];"
                 : "=r"(r[0]), "=r"(r[1]), "=r"(r[2]), "=r"(r[3]) : "r"(addr));
}

// ---------------- fused BN+ReLU + fp16 GEMM ----------------
// C[M=12544, N=192] = relu(x*s+t)[M, K] * W[N, K]^T ; grid 392 = 196 m x 2 n
__global__ __launch_bounds__(NTH, 3)
void gemm_k(const float* __restrict__ x,
            const float* __restrict__ gamma, const float* __restrict__ beta,
            const float* __restrict__ mean,  const float* __restrict__ var,
            float* __restrict__ out) {
    extern __shared__ char smem[];
    float2* bns = (float2*)(smem + SM_BNS);
    const uint32_t sA = smem_u32(smem) + SM_A;
    const uint32_t sB = smem_u32(smem) + SM_B;

    const int tid  = threadIdx.x;
    const int lane = tid & 31, warp = tid >> 5;     // 4 warps
    const int wm = warp & 1, wn = warp >> 1;        // 2 x 2 warp grid, tile 32x48
    const int g  = lane >> 2, tq = lane & 3;

    const int m0 = (blockIdx.x >> 1) * BM;
    const int n0 = (blockIdx.x & 1) * BN;

    // A loader: thread -> (m = tid&63, 32 k at kh*32), staged in two 16-k halves
    const int am = tid & 63, kh = tid >> 6;
    const int mg = m0 + am;
    const float* xp = x + (size_t)(mg / HW) * ((size_t)CIN * HW) + (mg % HW)
                        + (size_t)(kh * 32) * HW;

    const __half* bsrc = g_wh + (size_t)n0 * CIN;

    // ldmatrix per-thread offsets within a stage
    const uint32_t offA = (uint32_t)(wm * 32 + (lane & 15)) * RSTB + (uint32_t)(lane >> 4) * 16u;
    uint32_t offB[3];
    #pragma unroll
    for (int j = 0; j < 3; j++)
        offB[j] = (uint32_t)(wn * 48 + j * 16 + ((lane >> 4) << 3) + (lane & 7)) * RSTB
                + (uint32_t)((lane >> 3) & 1) * 16u;

    float acc[2][6][4] = {};
    float ar[16];
    uint32_t af[2][2][4], bf[2][3][4];     // double-buffered fragments

    // B cp.async for one chunk: 96 rows x 8 packets = 768 = 6 x 128
    auto issueB = [&](int c, uint32_t bb) {
        const __half* bw = bsrc + (size_t)c * BK;
        #pragma unroll
        for (int i = 0; i < 6; i++) {
            const int q = tid + i * NTH, r = q >> 3, p = q & 7;
            cp16(bb + r * RSTB + p * 16, bw + (size_t)r * CIN + p * 8);
        }
    };
    auto ldgA = [&](int c, int hf) {
        const float* xp2 = xp + (size_t)(c * BK + hf * 16) * HW;
        #pragma unroll
        for (int j = 0; j < 16; j++) ar[j] = __ldg(xp2 + (size_t)j * HW);
    };
    // BN+ReLU+cvt+STS from smem bns table (fast path, no global reads)
    auto stsA = [&](int c, int hf) {
        const int k0 = c * BK + kh * 32 + hf * 16;
        __half h[16];
        #pragma unroll
        for (int j = 0; j < 16; j++) {
            const float2 s = bns[k0 + j];
            h[j] = __float2half_rn(fmaxf(fmaf(ar[j], s.x, s.y), 0.f));
        }
        char* ab = smem + SM_A + (c & 1) * A_STAGE + am * RSTB + kh * 64 + hf * 32;
        *(uint4*)(ab)      = *(uint4*)&h[0];
        *(uint4*)(ab + 16) = *(uint4*)&h[8];
    };

    // load step-s fragments into buffer buf
    auto loadfrag = [&](uint32_t aBase, uint32_t bBase, int s, int buf) {
        ldm_x4(af[buf][0], aBase + offA + s * 32);
        ldm_x4(af[buf][1], aBase + offA + 16 * RSTB + s * 32);
        #pragma unroll
        for (int j = 0; j < 3; j++) ldm_x4(bf[buf][j], bBase + offB[j] + s * 32);
    };
    // issue the 12 MMAs for buffer buf
    auto mmastep = [&](int buf) {
        #pragma unroll
        for (int mi = 0; mi < 2; mi++)
            #pragma unroll
            for (int ni = 0; ni < 6; ni++) {
                const uint32_t* bp = &bf[buf][ni >> 1][(ni & 1) * 2];
                asm volatile(
                    "mma.sync.aligned.m16n8k16.row.col.f32.f16.f16.f32 "
                    "{%0,%1,%2,%3},{%4,%5,%6,%7},{%8,%9},{%0,%1,%2,%3};"
                    : "+f"(acc[mi][ni][0]), "+f"(acc[mi][ni][1]),
                      "+f"(acc[mi][ni][2]), "+f"(acc[mi][ni][3])
                    : "r"(af[buf][mi][0]), "r"(af[buf][mi][1]),
                      "r"(af[buf][mi][2]), "r"(af[buf][mi][3]),
                      "r"(bp[0]), "r"(bp[1]));
            }
    };

    // ---- prologue: bns table + stage chunk 0 ----
    issueB(0, sB);
    asm volatile("cp.async.commit_group;");
    for (int c = tid; c < CIN; c += NTH) {
        float inv = rsqrtf(var[c] + EPS_BN);
        float s = gamma[c] * inv;
        bns[c] = make_float2(s, fmaf(-mean[c], s, beta[c]));
    }
    __syncthreads();                                 // bns visible
    ldgA(0, 0); stsA(0, 0);
    ldgA(0, 1); stsA(0, 1);
    asm volatile("cp.async.wait_group 0;");
    __syncthreads();

    // ---- main loop (fragment double-buffered) ----
    #pragma unroll 1
    for (int t = 0; t < CHUNKS; t++) {
        const int cur = t & 1, nxt = cur ^ 1;
        const bool more = (t + 1 < CHUNKS);
        const uint32_t aBase = sA + cur * A_STAGE;
        const uint32_t bBase = sB + cur * B_STAGE;

        loadfrag(aBase, bBase, 0, 0);            // first step frags

        if (more) {
            ldgA(t + 1, 0);
            issueB(t + 1, sB + nxt * B_STAGE);
        }
        asm volatile("cp.async.commit_group;");

        loadfrag(aBase, bBase, 1, 1);            // prefetch s1
        mmastep(0);                              // compute s0
        if (more) { stsA(t + 1, 0); ldgA(t + 1, 1); }
        loadfrag(aBase, bBase, 2, 0);            // prefetch s2
        mmastep(1);                              // compute s1
        loadfrag(aBase, bBase, 3, 1);            // prefetch s3
        mmastep(0);                              // compute s2
        if (more) stsA(t + 1, 1);
        mmastep(1);                              // compute s3

        asm volatile("cp.async.wait_group 0;");
        __syncthreads();
    }

    // ---- epilogue: acc -> Cs[n][m] in smem -> coalesced STG ----
    float* Cs = (float*)smem;                    // 96 x 66 floats (reuses smem incl. bns)
    #pragma unroll
    for (int mi = 0; mi < 2; mi++)
        #pragma unroll
        for (int hh = 0; hh < 2; hh++) {
            const int mloc = wm * 32 + mi * 16 + g + hh * 8;
            #pragma unroll
            for (int ni = 0; ni < 6; ni++) {
                const int nloc = wn * 48 + ni * 8 + tq * 2;
                Cs[nloc * CST + mloc]       = acc[mi][ni][hh * 2 + 0];
                Cs[(nloc + 1) * CST + mloc] = acc[mi][ni][hh * 2 + 1];
            }
        }
    __syncthreads();

    // each warp writes 24 n-rows; lane covers m = 2*lane, 2*lane+1 (hw-contiguous)
    {
        const int mg0 = m0 + lane * 2;
        const int b0_ = mg0 / HW,        hw0 = mg0 - b0_ * HW;
        const int b1_ = (mg0 + 1) / HW,  hw1 = (mg0 + 1) - b1_ * HW;
        #pragma unroll
        for (int r = 0; r < 24; r++) {
            const int nn = n0 + warp * 24 + r;
            const float2 v = *(const float2*)&Cs[(warp * 24 + r) * CST + lane * 2];
            out[((size_t)b0_ * COUT + nn) * HW + hw0] = v.x;
            out[((size_t)b1_ * COUT + nn) * HW + hw1] = v.y;
        }
    }
}

extern "C" void kernel_launch(void* const* d_in, const int* in_sizes, int n_in,
                              void* d_out, int out_size) {
    const float* x     = (const float*)d_in[0];
    const float* gamma = (const float*)d_in[1];
    const float* beta  = (const float*)d_in[2];
    const float* mean  = (const float*)d_in[3];
    const float* var   = (const float*)d_in[4];
    const float* W     = (const float*)d_in[5];
    float* out = (float*)d_out;

    prep_w_k<<<(COUT * CIN + 255) / 256, 256>>>(W);
    cudaFuncSetAttribute(gemm_k, cudaFuncAttributeMaxDynamicSharedMemorySize, SMEM_TOTAL);
    gemm_k<<<(M_TOTAL / BM) * 2, NTH, SMEM_TOTAL>>>(x, gamma, beta, mean, var, out);
}

// round 17
// speedup vs baseline: 1.0887x; 1.0465x over previous
#include <cuda_runtime.h>
#include <cuda_fp16.h>
#include <cstdint>

// ---------------- problem constants ----------------
#define CIN     2112
#define COUT    192
#define HW      49
#define M_TOTAL 12544          // 256*49
#define BM      64
#define BN      96
#define BK      64
#define CHUNKS  33             // 2112/64
#define NTH     128            // 4 warps, warp tile 32x48
#define EPS_BN  1e-5f

// smem: row stride 144B (64 halfs + 16B pad; 16B-aligned, conflict-free)
#define RSTB    144
#define A_STAGE (BM * RSTB)            // 9216 B
#define B_STAGE (BN * RSTB)            // 13824 B
#define SM_BNS  0                      // float2[2112] = 16896 B
#define SM_A    16896                  // 2 stages
#define SM_B    (SM_A + 2 * A_STAGE)   // 2 stages
#define SMEM_TOTAL (SM_B + 2 * B_STAGE)  // 62976 B -> 3 CTAs/SM
#define CST     66                     // epilogue Cs row stride (floats)

// ---------------- persistent scratch ----------------
__device__ __half g_wh[COUT * CIN];    // W fp16, k-major

// vectorized: 4 halfs per thread, 396 blocks
__global__ void prep_w_k(const float* __restrict__ W) {
    int i = blockIdx.x * blockDim.x + threadIdx.x;   // 0 .. 101375
    if (i < (COUT * CIN) / 4) {
        float4 w = ((const float4*)W)[i];
        __half h[4] = { __float2half_rn(w.x), __float2half_rn(w.y),
                        __float2half_rn(w.z), __float2half_rn(w.w) };
        ((uint2*)g_wh)[i] = *(uint2*)h;
    }
}

// ---------------- helpers ----------------
__device__ __forceinline__ uint32_t smem_u32(const void* p) {
    uint32_t a;
    asm("{ .reg .u64 t; cvta.to.shared.u64 t, %1; cvt.u32.u64 %0, t; }" : "=r"(a) : "l"(p));
    return a;
}
__device__ __forceinline__ void cp16(uint32_t dst, const void* src) {
    asm volatile("cp.async.cg.shared.global [%0], [%1], 16;" :: "r"(dst), "l"(src));
}
__device__ __forceinline__ void ldm_x4(uint32_t* r, uint32_t addr) {
    asm volatile("ldmatrix.sync.aligned.m8n8.x4.shared.b16 {%0,%1,%2,%3}, [%4];"
                 : "=r"(r[0]), "=r"(r[1]), "=r"(r[2]), "=r"(r[3]) : "r"(addr));
}

// ---------------- fused BN+ReLU + fp16 GEMM (R11 configuration) ----------------
// C[M=12544, N=192] = relu(x*s+t)[M, K] * W[N, K]^T ; grid 392 = 196 m x 2 n
__global__ __launch_bounds__(NTH, 3)
void gemm_k(const float* __restrict__ x,
            const float* __restrict__ gamma, const float* __restrict__ beta,
            const float* __restrict__ mean,  const float* __restrict__ var,
            float* __restrict__ out) {
    extern __shared__ char smem[];
    float2* bns = (float2*)(smem + SM_BNS);
    const uint32_t sA = smem_u32(smem) + SM_A;
    const uint32_t sB = smem_u32(smem) + SM_B;

    const int tid  = threadIdx.x;
    const int lane = tid & 31, warp = tid >> 5;     // 4 warps
    const int wm = warp & 1, wn = warp >> 1;        // 2 x 2 warp grid, tile 32x48
    const int g  = lane >> 2, tq = lane & 3;

    const int m0 = (blockIdx.x >> 1) * BM;
    const int n0 = (blockIdx.x & 1) * BN;

    // A loader: thread -> (m = tid&63, 32 k at kh*32)
    const int am = tid & 63, kh = tid >> 6;
    const int mg = m0 + am;
    const float* xp = x + (size_t)(mg / HW) * ((size_t)CIN * HW) + (mg % HW)
                        + (size_t)(kh * 32) * HW;

    const __half* bsrc = g_wh + (size_t)n0 * CIN;

    // ldmatrix per-thread offsets within a stage
    const uint32_t offA = (uint32_t)(wm * 32 + (lane & 15)) * RSTB + (uint32_t)(lane >> 4) * 16u;
    uint32_t offB[3];
    #pragma unroll
    for (int j = 0; j < 3; j++)
        offB[j] = (uint32_t)(wn * 48 + j * 16 + ((lane >> 4) << 3) + (lane & 7)) * RSTB
                + (uint32_t)((lane >> 3) & 1) * 16u;

    float acc[2][6][4] = {};
    float ar[32];

    // B cp.async for one chunk: 96 rows x 8 packets = 768 = 6 x 128
    auto issueB = [&](int c, uint32_t bb) {
        const __half* bw = bsrc + (size_t)c * BK;
        #pragma unroll
        for (int i = 0; i < 6; i++) {
            const int q = tid + i * NTH, r = q >> 3, p = q & 7;
            cp16(bb + r * RSTB + p * 16, bw + (size_t)r * CIN + p * 8);
        }
    };
    // LDG 32 x-values of chunk c
    auto ldgA = [&](int c) {
        const float* xp2 = xp + (size_t)c * BK * HW;
        #pragma unroll
        for (int j = 0; j < 32; j++) ar[j] = __ldg(xp2 + (size_t)j * HW);
    };
    // BN+ReLU+cvt+STS chunk c from regs (bns via float4 pairs; k0 always even)
    auto stsA = [&](int c) {
        const int k0 = c * BK + kh * 32;
        const float4* b4 = (const float4*)(bns + k0);
        __half h[32];
        #pragma unroll
        for (int jj = 0; jj < 16; jj++) {
            const float4 sv = b4[jj];
            h[2 * jj]     = __float2half_rn(fmaxf(fmaf(ar[2 * jj],     sv.x, sv.y), 0.f));
            h[2 * jj + 1] = __float2half_rn(fmaxf(fmaf(ar[2 * jj + 1], sv.z, sv.w), 0.f));
        }
        char* ab = smem + SM_A + (c & 1) * A_STAGE + am * RSTB + kh * 64;
        #pragma unroll
        for (int i = 0; i < 4; i++)
            *(uint4*)(ab + i * 16) = *(uint4*)&h[i * 8];
    };

    // one k16 compute step
    auto step = [&](uint32_t aBase, uint32_t bBase, int s) {
        uint32_t a[2][4], b[3][4];
        ldm_x4(a[0], aBase + offA + s * 32);
        ldm_x4(a[1], aBase + offA + 16 * RSTB + s * 32);
        #pragma unroll
        for (int j = 0; j < 3; j++) ldm_x4(b[j], bBase + offB[j] + s * 32);
        #pragma unroll
        for (int mi = 0; mi < 2; mi++)
            #pragma unroll
            for (int ni = 0; ni < 6; ni++) {
                const uint32_t* bf = &b[ni >> 1][(ni & 1) * 2];
                asm volatile(
                    "mma.sync.aligned.m16n8k16.row.col.f32.f16.f16.f32 "
                    "{%0,%1,%2,%3},{%4,%5,%6,%7},{%8,%9},{%0,%1,%2,%3};"
                    : "+f"(acc[mi][ni][0]), "+f"(acc[mi][ni][1]),
                      "+f"(acc[mi][ni][2]), "+f"(acc[mi][ni][3])
                    : "r"(a[mi][0]), "r"(a[mi][1]), "r"(a[mi][2]), "r"(a[mi][3]),
                      "r"(bf[0]), "r"(bf[1]));
            }
    };

    // ---- prologue ----
    issueB(0, sB);
    asm volatile("cp.async.commit_group;");
    ldgA(0);
    for (int c = tid; c < CIN; c += NTH) {
        float inv = rsqrtf(var[c] + EPS_BN);
        float s = gamma[c] * inv;
        bns[c] = make_float2(s, fmaf(-mean[c], s, beta[c]));
    }
    __syncthreads();                                 // bns ready
    stsA(0);
    asm volatile("cp.async.wait_group 0;");
    __syncthreads();

    // ---- main loop (R11 structure): LDG A(t+1); cp B(t+1); compute(t); STS A(t+1); wait; sync
    #pragma unroll 1
    for (int t = 0; t < CHUNKS; t++) {
        const int cur = t & 1, nxt = cur ^ 1;
        const bool more = (t + 1 < CHUNKS);

        if (more) {
            ldgA(t + 1);
            issueB(t + 1, sB + nxt * B_STAGE);
        }
        asm volatile("cp.async.commit_group;");

        const uint32_t aBase = sA + cur * A_STAGE;
        const uint32_t bBase = sB + cur * B_STAGE;
        step(aBase, bBase, 0);
        step(aBase, bBase, 1);
        step(aBase, bBase, 2);
        step(aBase, bBase, 3);

        if (more) stsA(t + 1);
        asm volatile("cp.async.wait_group 0;");
        __syncthreads();
    }

    // ---- epilogue: acc -> Cs[n][m] in smem -> coalesced STG ----
    float* Cs = (float*)smem;                        // 96 x 66 floats (reuses smem)
    #pragma unroll
    for (int mi = 0; mi < 2; mi++)
        #pragma unroll
        for (int hh = 0; hh < 2; hh++) {
            const int mloc = wm * 32 + mi * 16 + g + hh * 8;
            #pragma unroll
            for (int ni = 0; ni < 6; ni++) {
                const int nloc = wn * 48 + ni * 8 + tq * 2;
                Cs[nloc * CST + mloc]       = acc[mi][ni][hh * 2 + 0];
                Cs[(nloc + 1) * CST + mloc] = acc[mi][ni][hh * 2 + 1];
            }
        }
    __syncthreads();

    // each warp writes 24 n-rows; lane covers m = 2*lane, 2*lane+1 (hw-contiguous)
    {
        const int mg0 = m0 + lane * 2;
        const int b0_ = mg0 / HW,        hw0 = mg0 - b0_ * HW;
        const int b1_ = (mg0 + 1) / HW,  hw1 = (mg0 + 1) - b1_ * HW;
        #pragma unroll
        for (int r = 0; r < 24; r++) {
            const int nn = n0 + warp * 24 + r;
            const float2 v = *(const float2*)&Cs[(warp * 24 + r) * CST + lane * 2];
            out[((size_t)b0_ * COUT + nn) * HW + hw0] = v.x;
            out[((size_t)b1_ * COUT + nn) * HW + hw1] = v.y;
        }
    }
}

extern "C" void kernel_launch(void* const* d_in, const int* in_sizes, int n_in,
                              void* d_out, int out_size) {
    const float* x     = (const float*)d_in[0];
    const float* gamma = (const float*)d_in[1];
    const float* beta  = (const float*)d_in[2];
    const float* mean  = (const float*)d_in[3];
    const float* var   = (const float*)d_in[4];
    const float* W     = (const float*)d_in[5];
    float* out = (float*)d_out;

    prep_w_k<<<(COUT * CIN / 4 + 255) / 256, 256>>>(W);
    cudaFuncSetAttribute(gemm_k, cudaFuncAttributeMaxDynamicSharedMemorySize, SMEM_TOTAL);
    gemm_k<<<(M_TOTAL / BM) * 2, NTH, SMEM_TOTAL>>>(x, gamma, beta, mean, var, out);
}